// round 8
// baseline (speedup 1.0000x reference)
#include <cuda_runtime.h>
#include <cstdint>

// ---------------------------------------------------------------------------
// Problem constants
// ---------------------------------------------------------------------------
constexpr int B_ = 8;
constexpr int C_ = 1024;     // M and K of both GEMMs
constexpr int T_ = 2048;     // N of both GEMMs
constexpr long NELEM = (long)B_ * C_ * T_;   // 16,777,216

// Fixed-point scales (powers of two)
#define S_W   262144.0f     // 2^18  (|W| <= 1/32 -> q <= 8192)
#define S_TAP 4096.0f       // 2^12  (clamp at 3.97 ~ 7.9 sigma)
#define S_FF1 8192.0f       // 2^13  (clamp at 1.99 ~ 6.8 sigma)
// epilogue scale factors: out = acc_hi*128^2/(Sw*Sx) + acc_mid*128/(Sw*Sx)
#define HI1  (16384.0f / (S_W * S_TAP))   // 2^-16
#define MID1 (  128.0f / (S_W * S_TAP))   // 2^-23
#define HI2  (16384.0f / (S_W * S_FF1))   // 2^-17
#define MID2 (  128.0f / (S_W * S_FF1))   // 2^-24

// d_out layout: [ret | tap | ff1 | ff2], each NELEM floats.

// ---------------------------------------------------------------------------
// Scratch (device globals)
//   X operands stored TRANSPOSED k-major: [B][T][C] int8 (hi, lo)
// ---------------------------------------------------------------------------
__device__ int8_t g_xah[(size_t)B_ * T_ * C_];
__device__ int8_t g_xal[(size_t)B_ * T_ * C_];
__device__ int8_t g_xbh[(size_t)B_ * T_ * C_];
__device__ int8_t g_xbl[(size_t)B_ * T_ * C_];
__device__ int8_t g_w1h[(size_t)C_ * C_];
__device__ int8_t g_w1l[(size_t)C_ * C_];
__device__ int8_t g_w2h[(size_t)C_ * C_];
__device__ int8_t g_w2l[(size_t)C_ * C_];

// ---------------------------------------------------------------------------
// helpers
// ---------------------------------------------------------------------------
__device__ __forceinline__ uint32_t smem_u32(const void* p) {
    uint32_t a;
    asm("{ .reg .u64 t; cvta.to.shared.u64 t, %1; cvt.u32.u64 %0, t; }"
        : "=r"(a) : "l"(p));
    return a;
}
__device__ __forceinline__ void cp_async16(uint32_t sdst, const void* gsrc) {
    asm volatile("cp.async.cg.shared.global [%0], [%1], 16;" :: "r"(sdst), "l"(gsrc));
}
__device__ __forceinline__ void cp_commit() {
    asm volatile("cp.async.commit_group;" ::: "memory");
}
template <int N>
__device__ __forceinline__ void cp_wait() {
    asm volatile("cp.async.wait_group %0;" :: "n"(N) : "memory");
}
__device__ __forceinline__ void ldsm_x4(uint32_t (&r)[4], uint32_t addr) {
    asm volatile("ldmatrix.sync.aligned.m8n8.x4.shared.b16 {%0,%1,%2,%3}, [%4];"
        : "=r"(r[0]), "=r"(r[1]), "=r"(r[2]), "=r"(r[3]) : "r"(addr));
}
// int8 IMMA: D(s32) += A(s8) * B(s8), m16n8k32
__device__ __forceinline__ void mma_s8(int (&d)[4],
                                       const uint32_t (&a)[4],
                                       const uint32_t* b) {
    asm volatile(
        "mma.sync.aligned.m16n8k32.row.col.s32.s8.s8.s32 "
        "{%0,%1,%2,%3}, {%4,%5,%6,%7}, {%8,%9}, {%0,%1,%2,%3};"
        : "+r"(d[0]), "+r"(d[1]), "+r"(d[2]), "+r"(d[3])
        : "r"(a[0]), "r"(a[1]), "r"(a[2]), "r"(a[3]), "r"(b[0]), "r"(b[1]));
}

// 15-bit fixed-point split: v ~= (hi*128 + lo)/S, hi,lo in s8
__device__ __forceinline__ void quant15(float v, float S, int8_t& hi, int8_t& lo) {
    int q = __float2int_rn(v * S);
    q = max(-16320, min(16255, q));
    int h = (q + 64) >> 7;
    hi = (int8_t)h;
    lo = (int8_t)(q - (h << 7));
}

// ---------------------------------------------------------------------------
// Kernel: both W matrices -> int8 hi/lo (row-major [M,K], natural layout)
// ---------------------------------------------------------------------------
__global__ void wquant_kernel(const float* __restrict__ W1,
                              const float* __restrict__ W2)
{
    int i = blockIdx.x * 256 + threadIdx.x;
    int8_t h, l;
    quant15(W1[i], S_W, h, l); g_w1h[i] = h; g_w1l[i] = l;
    quant15(W2[i], S_W, h, l); g_w2h[i] = h; g_w2l[i] = l;
}

// ---------------------------------------------------------------------------
// Kernel: 4:1 mean pool -> tap fp32 [B,C,T] + quantized TRANSPOSED int8 [B,T,C]
// tile: 64 c x 32 t, block (32,8)
// ---------------------------------------------------------------------------
__global__ void pool_trq_kernel(const float* __restrict__ x, float* __restrict__ tap)
{
    __shared__ float s[64][33];
    const int b = blockIdx.z, c0 = blockIdx.y * 64, t0 = blockIdx.x * 32;
    const int tx = threadIdx.x, ty = threadIdx.y;
    const float4* x4 = reinterpret_cast<const float4*>(x);
    #pragma unroll
    for (int i = 0; i < 8; i++) {
        int cl = ty + i * 8;
        int c = c0 + cl;
        float4 v = x4[((size_t)b * C_ + c) * T_ + t0 + tx];
        float m = 0.25f * (v.x + v.y + v.z + v.w);
        s[cl][tx] = m;
        tap[((size_t)b * C_ + c) * T_ + t0 + tx] = m;
    }
    __syncthreads();
    const int tid = ty * 32 + tx;
    const int tl = tid >> 3;          // 0..31 local t
    const int cg = tid & 7;           // 8-channel group
    int8_t hh[8], ll[8];
    #pragma unroll
    for (int j = 0; j < 8; j++)
        quant15(s[cg * 8 + j][tl], S_TAP, hh[j], ll[j]);
    size_t o = ((size_t)b * T_ + t0 + tl) * C_ + c0 + cg * 8;
    *reinterpret_cast<uint2*>(g_xah + o) = *reinterpret_cast<uint2*>(hh);
    *reinterpret_cast<uint2*>(g_xal + o) = *reinterpret_cast<uint2*>(ll);
}

// ---------------------------------------------------------------------------
// Kernel: ff1 fp32 [B,C,T] -> quantized TRANSPOSED int8 [B,T,C]
// ---------------------------------------------------------------------------
__global__ void tconvq_kernel(const float* __restrict__ ff)
{
    __shared__ float s[64][33];
    const int b = blockIdx.z, c0 = blockIdx.y * 64, t0 = blockIdx.x * 32;
    const int tx = threadIdx.x, ty = threadIdx.y;
    #pragma unroll
    for (int i = 0; i < 8; i++) {
        int cl = ty + i * 8;
        s[cl][tx] = ff[((size_t)b * C_ + c0 + cl) * T_ + t0 + tx];
    }
    __syncthreads();
    const int tid = ty * 32 + tx;
    const int tl = tid >> 3;
    const int cg = tid & 7;
    int8_t hh[8], ll[8];
    #pragma unroll
    for (int j = 0; j < 8; j++)
        quant15(s[cg * 8 + j][tl], S_FF1, hh[j], ll[j]);
    size_t o = ((size_t)b * T_ + t0 + tl) * C_ + c0 + cg * 8;
    *reinterpret_cast<uint2*>(g_xbh + o) = *reinterpret_cast<uint2*>(hh);
    *reinterpret_cast<uint2*>(g_xbl + o) = *reinterpret_cast<uint2*>(ll);
}

// ---------------------------------------------------------------------------
// GEMM (int8 IMMA, 3 terms, exact s32 accumulation):
//   out[b][m][n] = [ acchh*128^2 + (acchl+acclh)*128 ] / (Sw*Sx) + bias[m]
// CTA tile 128(M) x 128(N), KC=64, 4-stage cp.async pipeline, 512 threads,
// 16 warps in 4(M) x 4(N) grid, warp tile 32x32.
// A: W int8 [M,K] row-major; B: X^T int8 [N,K] k-major (both hi+lo).
// ---------------------------------------------------------------------------
constexpr int KC = 64;
constexpr int R_STR = 80;                  // bytes per 64B row + 16B pad
constexpr int OF_AH = 0;
constexpr int OF_AL = 128 * R_STR;         // 10240
constexpr int OF_BH = 2 * 128 * R_STR;     // 20480
constexpr int OF_BL = 3 * 128 * R_STR;     // 30720
constexpr int STAGE_BYTES = 4 * 128 * R_STR;      // 40960
constexpr int STAGES = 4;
constexpr int GEMM_SMEM = STAGES * STAGE_BYTES;   // 163840
constexpr int NCHUNK = C_ / KC;                   // 16

__global__ __launch_bounds__(512, 1)
void gemm_kernel(const int8_t* __restrict__ Wh,
                 const int8_t* __restrict__ Wl,
                 const int8_t* __restrict__ Xh,     // [B][T][C]
                 const int8_t* __restrict__ Xl,
                 const float*  __restrict__ bias,
                 float* __restrict__ out,           // [B][C][T]
                 float scale_hi, float scale_mid)
{
    extern __shared__ __align__(128) char smem[];
    const uint32_t sb = smem_u32(smem);

    const int tid  = threadIdx.x;
    const int wid  = tid >> 5;
    const int lane = tid & 31;
    const int bn = blockIdx.x * 128;
    const int bm = blockIdx.y * 128;
    const int bz = blockIdx.z;

    const int wm = (wid & 3) * 32;     // 4 warps over M
    const int wn = (wid >> 2) * 32;    // 4 warps over N

    // cp.async: 512 threads, each 1 cp16 per operand per stage
    const int r_ = tid >> 2;           // 0..127 row
    const int c_ = tid & 3;            // 16B chunk in 64B row

    const int8_t* gAh = Wh + (size_t)(bm + r_) * C_ + c_ * 16;
    const int8_t* gAl = Wl + (size_t)(bm + r_) * C_ + c_ * 16;
    const int8_t* gBh = Xh + ((size_t)bz * T_ + bn + r_) * C_ + c_ * 16;
    const int8_t* gBl = Xl + ((size_t)bz * T_ + bn + r_) * C_ + c_ * 16;
    const uint32_t sOff = (uint32_t)(r_ * R_STR + c_ * 16);

    auto load_stage = [&](int ch, int stg) {
        const int k0 = ch * KC;
        const uint32_t st = sb + stg * STAGE_BYTES;
        cp_async16(st + OF_AH + sOff, gAh + k0);
        cp_async16(st + OF_AL + sOff, gAl + k0);
        cp_async16(st + OF_BH + sOff, gBh + k0);
        cp_async16(st + OF_BL + sOff, gBl + k0);
        cp_commit();
    };

    int acc1[2][4][4];   // hi*hi  (scale 128^2)
    int acc2[2][4][4];   // hi*lo + lo*hi  (scale 128)
    #pragma unroll
    for (int i = 0; i < 2; i++)
        #pragma unroll
        for (int j = 0; j < 4; j++)
            #pragma unroll
            for (int k = 0; k < 4; k++) { acc1[i][j][k] = 0; acc2[i][j][k] = 0; }

    load_stage(0, 0);
    load_stage(1, 1);
    load_stage(2, 2);

    const int lRow = lane & 15;
    const int lHalf = (lane >> 4) * 16;   // 16B half selector

    for (int ch = 0; ch < NCHUNK; ch++) {
        cp_wait<STAGES - 2>();
        __syncthreads();

        if (ch + STAGES - 1 < NCHUNK)
            load_stage(ch + STAGES - 1, (ch + STAGES - 1) % STAGES);
        else
            cp_commit();

        const uint32_t st = sb + (ch % STAGES) * STAGE_BYTES;

        #pragma unroll
        for (int ks = 0; ks < 2; ks++) {   // two k32 steps per 64B row
            // B fragments: warp's 32 n in two 16-n ldsm groups, hi+lo
            uint32_t bh[4][2], bl[4][2];
            #pragma unroll
            for (int nq = 0; nq < 2; nq++) {
                uint32_t off = (uint32_t)((wn + nq * 16 + lRow) * R_STR
                                          + ks * 32 + lHalf);
                uint32_t r[4];
                ldsm_x4(r, st + OF_BH + off);
                bh[nq * 2 + 0][0] = r[0]; bh[nq * 2 + 0][1] = r[2];
                bh[nq * 2 + 1][0] = r[1]; bh[nq * 2 + 1][1] = r[3];
                ldsm_x4(r, st + OF_BL + off);
                bl[nq * 2 + 0][0] = r[0]; bl[nq * 2 + 0][1] = r[2];
                bl[nq * 2 + 1][0] = r[1]; bl[nq * 2 + 1][1] = r[3];
            }
            #pragma unroll
            for (int mb = 0; mb < 2; mb++) {
                uint32_t ah[4], al[4];
                uint32_t offA = (uint32_t)((wm + mb * 16 + lRow) * R_STR
                                           + ks * 32 + lHalf);
                ldsm_x4(ah, st + OF_AH + offA);
                ldsm_x4(al, st + OF_AL + offA);
                #pragma unroll
                for (int nb = 0; nb < 4; nb++) {
                    mma_s8(acc1[mb][nb], ah, bh[nb]);
                    mma_s8(acc2[mb][nb], ah, bl[nb]);
                    mma_s8(acc2[mb][nb], al, bh[nb]);
                }
            }
        }
    }

    // epilogue: combine terms, add bias, store fp32
    const int r_lo = lane >> 2;
    const int c_lo = (lane & 3) * 2;
    #pragma unroll
    for (int mb = 0; mb < 2; mb++) {
        int gr0 = bm + wm + mb * 16 + r_lo;
        int gr1 = gr0 + 8;
        float bv0 = bias[gr0];
        float bv1 = bias[gr1];
        size_t ro0 = ((size_t)bz * C_ + gr0) * T_ + bn + wn + c_lo;
        size_t ro1 = ((size_t)bz * C_ + gr1) * T_ + bn + wn + c_lo;
        #pragma unroll
        for (int nb = 0; nb < 4; nb++) {
            float v00 = fmaf((float)acc1[mb][nb][0], scale_hi,
                        fmaf((float)acc2[mb][nb][0], scale_mid, bv0));
            float v01 = fmaf((float)acc1[mb][nb][1], scale_hi,
                        fmaf((float)acc2[mb][nb][1], scale_mid, bv0));
            float v10 = fmaf((float)acc1[mb][nb][2], scale_hi,
                        fmaf((float)acc2[mb][nb][2], scale_mid, bv1));
            float v11 = fmaf((float)acc1[mb][nb][3], scale_hi,
                        fmaf((float)acc2[mb][nb][3], scale_mid, bv1));
            *reinterpret_cast<float2*>(out + ro0 + nb * 8) = make_float2(v00, v01);
            *reinterpret_cast<float2*>(out + ro1 + nb * 8) = make_float2(v10, v11);
        }
    }
}

// ---------------------------------------------------------------------------
// Kernel: causal windowed mean, via per-group partial sums.
// ---------------------------------------------------------------------------
__global__ void window_kernel(const float* __restrict__ ff2, float* __restrict__ ret)
{
    __shared__ float s[T_];
    __shared__ float pre[T_ / 4];
    const size_t row = blockIdx.x;
    const float4* p4 = reinterpret_cast<const float4*>(ff2 + row * T_);
    float4* s4 = reinterpret_cast<float4*>(s);
    #pragma unroll
    for (int i = 0; i < 2; i++) {
        int idx = threadIdx.x + i * 256;
        float4 v = p4[idx];
        s4[idx] = v;
        pre[idx] = v.x + v.y + v.z + v.w;
    }
    __syncthreads();
    float4* r4 = reinterpret_cast<float4*>(ret + row * T_);
    #pragma unroll
    for (int i = 0; i < 2; i++) {
        int g = threadIdx.x + i * 256;
        float avg;
        if (g >= 4) {
            float sum = s[4 * g] - s[4 * g - 16]
                      + pre[g - 4] + pre[g - 3] + pre[g - 2] + pre[g - 1];
            avg = sum * 0.0625f;
        } else {
            float sum = s[4 * g];
            for (int q = 0; q < g; q++) sum += pre[q];
            avg = sum / (float)(4 * g + 1);
        }
        r4[g] = make_float4(avg, avg, avg, avg);
    }
}

// ---------------------------------------------------------------------------
// Launcher
// ---------------------------------------------------------------------------
extern "C" void kernel_launch(void* const* d_in, const int* in_sizes, int n_in,
                              void* d_out, int out_size)
{
    const float* x  = (const float*)d_in[0];
    const float* W1 = (const float*)d_in[1];
    const float* b1 = (const float*)d_in[2];
    const float* W2 = (const float*)d_in[3];
    const float* b2 = (const float*)d_in[4];

    float* out = (float*)d_out;
    float* ret = out;
    float* tap = out + NELEM;
    float* ff1 = out + 2 * NELEM;
    float* ff2 = out + 3 * NELEM;

    cudaFuncSetAttribute(gemm_kernel,
                         cudaFuncAttributeMaxDynamicSharedMemorySize, GEMM_SMEM);

    static int8_t *xah = nullptr, *xal, *xbh, *xbl, *w1h, *w1l, *w2h, *w2l;
    if (!xah) {
        cudaGetSymbolAddress((void**)&xah, g_xah);
        cudaGetSymbolAddress((void**)&xal, g_xal);
        cudaGetSymbolAddress((void**)&xbh, g_xbh);
        cudaGetSymbolAddress((void**)&xbl, g_xbl);
        cudaGetSymbolAddress((void**)&w1h, g_w1h);
        cudaGetSymbolAddress((void**)&w1l, g_w1l);
        cudaGetSymbolAddress((void**)&w2h, g_w2h);
        cudaGetSymbolAddress((void**)&w2l, g_w2l);
    }

    // 1. W quant splits
    wquant_kernel<<<(C_ * C_) / 256, 256>>>(W1, W2);

    // 2. pool -> tap fp32 + quantized transposed xa
    {
        dim3 grid(T_ / 32, C_ / 64, B_);
        pool_trq_kernel<<<grid, dim3(32, 8)>>>(x, tap);
    }

    // 3. ff1 = W1 @ tap + b1
    {
        dim3 grid(T_ / 128, C_ / 128, B_);
        gemm_kernel<<<grid, 512, GEMM_SMEM>>>(w1h, w1l, xah, xal, b1, ff1,
                                              HI1, MID1);
    }

    // 4. ff1 -> quantized transposed xb
    {
        dim3 grid(T_ / 32, C_ / 64, B_);
        tconvq_kernel<<<grid, dim3(32, 8)>>>(ff1);
    }

    // 5. ff2 = W2 @ ff1 + b2
    {
        dim3 grid(T_ / 128, C_ / 128, B_);
        gemm_kernel<<<grid, 512, GEMM_SMEM>>>(w2h, w2l, xbh, xbl, b2, ff2,
                                              HI2, MID2);
    }

    // 6. windowed mean + stride-4 broadcast -> ret
    window_kernel<<<B_ * C_, 256>>>(ff2, ret);
}

// round 9
// speedup vs baseline: 4.3111x; 4.3111x over previous
#include <cuda_runtime.h>
#include <cuda_fp16.h>
#include <cstdint>

// ---------------------------------------------------------------------------
// Problem constants
// ---------------------------------------------------------------------------
constexpr int B_ = 8;
constexpr int C_ = 1024;     // M and K of both GEMMs
constexpr int T_ = 2048;     // N of both GEMMs
constexpr long NELEM = (long)B_ * C_ * T_;   // 16,777,216

// d_out layout: [ret | tap | ff1 | ff2], each NELEM floats.

// ---------------------------------------------------------------------------
// Scratch (device globals)
// ---------------------------------------------------------------------------
__device__ __half g_xa[(size_t)B_ * C_ * T_];   // fp16(tap)  : B of GEMM1
__device__ __half g_xb[(size_t)B_ * C_ * T_];   // fp16(ff1)  : B of GEMM2
__device__ __half g_w1[(size_t)C_ * C_];
__device__ __half g_w2[(size_t)C_ * C_];

// ---------------------------------------------------------------------------
// helpers
// ---------------------------------------------------------------------------
__device__ __forceinline__ uint32_t smem_u32(const void* p) {
    uint32_t a;
    asm("{ .reg .u64 t; cvta.to.shared.u64 t, %1; cvt.u32.u64 %0, t; }"
        : "=r"(a) : "l"(p));
    return a;
}
__device__ __forceinline__ void cp_async16(uint32_t sdst, const void* gsrc) {
    asm volatile("cp.async.cg.shared.global [%0], [%1], 16;" :: "r"(sdst), "l"(gsrc));
}
__device__ __forceinline__ void cp_commit() {
    asm volatile("cp.async.commit_group;" ::: "memory");
}
template <int N>
__device__ __forceinline__ void cp_wait() {
    asm volatile("cp.async.wait_group %0;" :: "n"(N) : "memory");
}
__device__ __forceinline__ void ldsm_x4(uint32_t (&r)[4], uint32_t addr) {
    asm volatile("ldmatrix.sync.aligned.m8n8.x4.shared.b16 {%0,%1,%2,%3}, [%4];"
        : "=r"(r[0]), "=r"(r[1]), "=r"(r[2]), "=r"(r[3]) : "r"(addr));
}
__device__ __forceinline__ void ldsm_x4t(uint32_t (&r)[4], uint32_t addr) {
    asm volatile("ldmatrix.sync.aligned.m8n8.x4.trans.shared.b16 {%0,%1,%2,%3}, [%4];"
        : "=r"(r[0]), "=r"(r[1]), "=r"(r[2]), "=r"(r[3]) : "r"(addr));
}
__device__ __forceinline__ void mma_f16(float (&d)[4],
                                        const uint32_t (&a)[4],
                                        const uint32_t* b) {
    asm volatile(
        "mma.sync.aligned.m16n8k16.row.col.f32.f16.f16.f32 "
        "{%0,%1,%2,%3}, {%4,%5,%6,%7}, {%8,%9}, {%0,%1,%2,%3};"
        : "+f"(d[0]), "+f"(d[1]), "+f"(d[2]), "+f"(d[3])
        : "r"(a[0]), "r"(a[1]), "r"(a[2]), "r"(a[3]), "r"(b[0]), "r"(b[1]));
}

// ---------------------------------------------------------------------------
// Kernel: W1, W2 -> fp16 (single term)
// ---------------------------------------------------------------------------
__global__ void wconv_kernel(const float* __restrict__ W1,
                             const float* __restrict__ W2)
{
    int i = blockIdx.x * 256 + threadIdx.x;
    g_w1[i] = __float2half(W1[i]);
    g_w2[i] = __float2half(W2[i]);
}

// ---------------------------------------------------------------------------
// Kernel: 4:1 mean pool -> tap (fp32) + fp16 copy into g_xa
// ---------------------------------------------------------------------------
__global__ void pool_kernel(const float* __restrict__ x, float* __restrict__ tap)
{
    long i = (long)blockIdx.x * blockDim.x + threadIdx.x;
    if (i >= NELEM) return;
    float4 v = reinterpret_cast<const float4*>(x)[i];
    float m = 0.25f * (v.x + v.y + v.z + v.w);
    tap[i] = m;
    g_xa[i] = __float2half(m);
}

// ---------------------------------------------------------------------------
// GEMM (single-term fp16 HMMA, f32 accumulate):
//   out[b][m][n] = sum_k W[m][k] * Xh[b][k][n] + bias[m]
// CTA tile 128(M) x 256(N), KC=32, 4-stage cp.async pipeline, 512 threads,
// 16 warps in 4(M) x 4(N) grid, warp tile 32x64. One barrier per chunk.
// ---------------------------------------------------------------------------
constexpr int KC = 32;
constexpr int A_STR = 80;                 // bytes per A row (64 + 16 pad)
constexpr int B_STR = 528;                // bytes per B row (512 + 16 pad)
constexpr int OF_A = 0;
constexpr int OF_B = 128 * A_STR;         // 10240
constexpr int STAGE_BYTES = OF_B + KC * B_STR;    // 27136
constexpr int STAGES = 4;
constexpr int GEMM_SMEM = STAGES * STAGE_BYTES;   // 108544
constexpr int NCHUNK = C_ / KC;                   // 32

__global__ __launch_bounds__(512, 1)
void gemm_kernel(const __half* __restrict__ W,
                 const __half* __restrict__ Xh,     // [B][C][T]
                 const float*  __restrict__ bias,
                 float* __restrict__ out,           // [B][C][T]
                 __half* __restrict__ out_h)        // nullable fp16 mirror
{
    extern __shared__ __align__(128) char smem[];
    const uint32_t sb = smem_u32(smem);

    const int tid  = threadIdx.x;
    const int wid  = tid >> 5;
    const int lane = tid & 31;
    const int bn = blockIdx.x * 256;
    const int bm = blockIdx.y * 128;
    const int bz = blockIdx.z;

    const int wm = (wid & 3) * 32;     // 4 warps over M
    const int wn = (wid >> 2) * 64;    // 4 warps over N

    const __half* Xb = Xh + (size_t)bz * C_ * T_;

    // cp.async task mappings (512 threads)
    const int a_r = tid >> 2;            // 0..127 : A row
    const int a_c = tid & 3;             // 16B chunk in A row
    const int b_k = tid >> 5;            // 0..15 : B row base (2 iters -> 32)
    const int b_c = tid & 31;            // 16B chunk in B row

    auto load_stage = [&](int ch, int stg) {
        const int k0 = ch * KC;
        const uint32_t st = sb + stg * STAGE_BYTES;
        {
            uint32_t sd = st + OF_A + a_r * A_STR + a_c * 16;
            cp_async16(sd, W + (size_t)(bm + a_r) * C_ + k0 + a_c * 8);
        }
        #pragma unroll
        for (int i = 0; i < 2; i++) {
            int kr = b_k + i * 16;
            uint32_t sd = st + OF_B + kr * B_STR + b_c * 16;
            cp_async16(sd, Xb + (size_t)(k0 + kr) * T_ + bn + b_c * 8);
        }
        cp_commit();
    };

    float acc[2][8][4];
    #pragma unroll
    for (int i = 0; i < 2; i++)
        #pragma unroll
        for (int j = 0; j < 8; j++)
            #pragma unroll
            for (int k = 0; k < 4; k++)
                acc[i][j][k] = 0.0f;

    // prologue
    load_stage(0, 0);
    load_stage(1, 1);
    load_stage(2, 2);

    const int lA_row = lane & 15;
    const int lA_kb  = (lane >> 4) * 16;
    const int lB_row = lane & 15;
    const int lB_nc  = (lane >> 4) * 8;

    for (int ch = 0; ch < NCHUNK; ch++) {
        cp_wait<STAGES - 2>();
        __syncthreads();

        if (ch + STAGES - 1 < NCHUNK)
            load_stage(ch + STAGES - 1, (ch + STAGES - 1) % STAGES);
        else
            cp_commit();   // keep group counts consistent

        const uint32_t st = sb + (ch % STAGES) * STAGE_BYTES;

        #pragma unroll
        for (int ks = 0; ks < 2; ks++) {
            // B fragments: warp's 64 cols = 4 ldsm_x4t
            uint32_t b[8][2];
            #pragma unroll
            for (int nq = 0; nq < 4; nq++) {
                uint32_t r[4];
                uint32_t off = (uint32_t)((ks * 16 + lB_row) * B_STR
                                          + (wn + nq * 16 + lB_nc) * 2);
                ldsm_x4t(r, st + OF_B + off);
                b[nq * 2 + 0][0] = r[0]; b[nq * 2 + 0][1] = r[1];
                b[nq * 2 + 1][0] = r[2]; b[nq * 2 + 1][1] = r[3];
            }
            // A fragments per 16-row block, single term
            #pragma unroll
            for (int mb = 0; mb < 2; mb++) {
                uint32_t a4[4];
                uint32_t offA = (uint32_t)((wm + mb * 16 + lA_row) * A_STR
                                           + ks * 32 + lA_kb);
                ldsm_x4(a4, st + OF_A + offA);
                #pragma unroll
                for (int nb = 0; nb < 8; nb++)
                    mma_f16(acc[mb][nb], a4, b[nb]);
            }
        }
        // single barrier per chunk (top of loop) is sufficient.
    }

    // epilogue: bias + fp32 store (+ optional fp16 mirror)
    const int r_lo = lane >> 2;
    const int c_lo = (lane & 3) * 2;
    #pragma unroll
    for (int mb = 0; mb < 2; mb++) {
        int gr0 = bm + wm + mb * 16 + r_lo;
        int gr1 = gr0 + 8;
        float bv0 = bias[gr0];
        float bv1 = bias[gr1];
        size_t ro0 = ((size_t)bz * C_ + gr0) * T_ + bn + wn + c_lo;
        size_t ro1 = ((size_t)bz * C_ + gr1) * T_ + bn + wn + c_lo;
        #pragma unroll
        for (int nb = 0; nb < 8; nb++) {
            float v00 = acc[mb][nb][0] + bv0, v01 = acc[mb][nb][1] + bv0;
            float v10 = acc[mb][nb][2] + bv1, v11 = acc[mb][nb][3] + bv1;
            *reinterpret_cast<float2*>(out + ro0 + nb * 8) = make_float2(v00, v01);
            *reinterpret_cast<float2*>(out + ro1 + nb * 8) = make_float2(v10, v11);
            if (out_h) {
                __half2 h0; h0.x = __float2half(v00); h0.y = __float2half(v01);
                __half2 h1; h1.x = __float2half(v10); h1.y = __float2half(v11);
                *reinterpret_cast<__half2*>(out_h + ro0 + nb * 8) = h0;
                *reinterpret_cast<__half2*>(out_h + ro1 + nb * 8) = h1;
            }
        }
    }
}

// ---------------------------------------------------------------------------
// Kernel: causal windowed mean, via per-group partial sums.
//   pre[g] = sum of ff2[4g .. 4g+3]
//   g < 4 : sum = pre[0..g-1] + s[4g]               (L = 4g+1)
//   g >= 4: sum = s[4g] - s[4g-16] + pre[g-4..g-1]  (L = 16)
// ---------------------------------------------------------------------------
__global__ void window_kernel(const float* __restrict__ ff2, float* __restrict__ ret)
{
    __shared__ float s[T_];
    __shared__ float pre[T_ / 4];
    const size_t row = blockIdx.x;
    const float4* p4 = reinterpret_cast<const float4*>(ff2 + row * T_);
    float4* s4 = reinterpret_cast<float4*>(s);
    #pragma unroll
    for (int i = 0; i < 2; i++) {
        int idx = threadIdx.x + i * 256;
        float4 v = p4[idx];
        s4[idx] = v;
        pre[idx] = v.x + v.y + v.z + v.w;
    }
    __syncthreads();
    float4* r4 = reinterpret_cast<float4*>(ret + row * T_);
    #pragma unroll
    for (int i = 0; i < 2; i++) {
        int g = threadIdx.x + i * 256;
        float avg;
        if (g >= 4) {
            float sum = s[4 * g] - s[4 * g - 16]
                      + pre[g - 4] + pre[g - 3] + pre[g - 2] + pre[g - 1];
            avg = sum * 0.0625f;
        } else {
            float sum = s[4 * g];
            for (int q = 0; q < g; q++) sum += pre[q];
            avg = sum / (float)(4 * g + 1);
        }
        r4[g] = make_float4(avg, avg, avg, avg);
    }
}

// ---------------------------------------------------------------------------
// Launcher
// ---------------------------------------------------------------------------
extern "C" void kernel_launch(void* const* d_in, const int* in_sizes, int n_in,
                              void* d_out, int out_size)
{
    const float* x  = (const float*)d_in[0];
    const float* W1 = (const float*)d_in[1];
    const float* b1 = (const float*)d_in[2];
    const float* W2 = (const float*)d_in[3];
    const float* b2 = (const float*)d_in[4];

    float* out = (float*)d_out;
    float* ret = out;
    float* tap = out + NELEM;
    float* ff1 = out + 2 * NELEM;
    float* ff2 = out + 3 * NELEM;

    cudaFuncSetAttribute(gemm_kernel,
                         cudaFuncAttributeMaxDynamicSharedMemorySize, GEMM_SMEM);

    static __half *xa = nullptr, *xb, *w1, *w2;
    if (!xa) {
        cudaGetSymbolAddress((void**)&xa, g_xa);
        cudaGetSymbolAddress((void**)&xb, g_xb);
        cudaGetSymbolAddress((void**)&w1, g_w1);
        cudaGetSymbolAddress((void**)&w2, g_w2);
    }

    // 1. W -> fp16
    wconv_kernel<<<(C_ * C_) / 256, 256>>>(W1, W2);

    // 2. pool -> tap fp32 + g_xa fp16
    pool_kernel<<<(int)(NELEM / 256), 256>>>(x, tap);

    // 3. ff1 = W1 @ tap + b1   (writes ff1 fp32 + g_xb fp16)
    {
        dim3 grid(T_ / 256, C_ / 128, B_);
        gemm_kernel<<<grid, 512, GEMM_SMEM>>>(w1, xa, b1, ff1, xb);
    }

    // 4. ff2 = W2 @ ff1 + b2
    {
        dim3 grid(T_ / 256, C_ / 128, B_);
        gemm_kernel<<<grid, 512, GEMM_SMEM>>>(w2, xb, b2, ff2, nullptr);
    }

    // 5. windowed mean + stride-4 broadcast -> ret
    window_kernel<<<B_ * C_, 256>>>(ff2, ret);
}

// round 10
// speedup vs baseline: 4.6238x; 1.0725x over previous
#include <cuda_runtime.h>
#include <cuda_fp16.h>
#include <cstdint>

// ---------------------------------------------------------------------------
// Problem constants
// ---------------------------------------------------------------------------
constexpr int B_ = 8;
constexpr int C_ = 1024;     // M and K of both GEMMs
constexpr int T_ = 2048;     // N of both GEMMs
constexpr long NELEM = (long)B_ * C_ * T_;   // 16,777,216

// d_out layout: [ret | tap | ff1 | ff2], each NELEM floats.

// ---------------------------------------------------------------------------
// Scratch (device globals)
// ---------------------------------------------------------------------------
__device__ __half g_xa[(size_t)B_ * C_ * T_];   // fp16(tap) : shared B operand
__device__ __half g_w1[(size_t)C_ * C_];
__device__ __half g_w2[(size_t)C_ * C_];
__device__ __half g_w12[(size_t)C_ * C_];       // fp16(W2 @ W1)
__device__ float  g_b12[C_];                    // W2 @ b1 + b2

// ---------------------------------------------------------------------------
// helpers
// ---------------------------------------------------------------------------
__device__ __forceinline__ uint32_t smem_u32(const void* p) {
    uint32_t a;
    asm("{ .reg .u64 t; cvta.to.shared.u64 t, %1; cvt.u32.u64 %0, t; }"
        : "=r"(a) : "l"(p));
    return a;
}
__device__ __forceinline__ void cp_async16(uint32_t sdst, const void* gsrc) {
    asm volatile("cp.async.cg.shared.global [%0], [%1], 16;" :: "r"(sdst), "l"(gsrc));
}
__device__ __forceinline__ void cp_commit() {
    asm volatile("cp.async.commit_group;" ::: "memory");
}
template <int N>
__device__ __forceinline__ void cp_wait() {
    asm volatile("cp.async.wait_group %0;" :: "n"(N) : "memory");
}
__device__ __forceinline__ void ldsm_x4(uint32_t (&r)[4], uint32_t addr) {
    asm volatile("ldmatrix.sync.aligned.m8n8.x4.shared.b16 {%0,%1,%2,%3}, [%4];"
        : "=r"(r[0]), "=r"(r[1]), "=r"(r[2]), "=r"(r[3]) : "r"(addr));
}
__device__ __forceinline__ void ldsm_x4t(uint32_t (&r)[4], uint32_t addr) {
    asm volatile("ldmatrix.sync.aligned.m8n8.x4.trans.shared.b16 {%0,%1,%2,%3}, [%4];"
        : "=r"(r[0]), "=r"(r[1]), "=r"(r[2]), "=r"(r[3]) : "r"(addr));
}
__device__ __forceinline__ void mma_f16(float (&d)[4],
                                        const uint32_t (&a)[4],
                                        const uint32_t* b) {
    asm volatile(
        "mma.sync.aligned.m16n8k16.row.col.f32.f16.f16.f32 "
        "{%0,%1,%2,%3}, {%4,%5,%6,%7}, {%8,%9}, {%0,%1,%2,%3};"
        : "+f"(d[0]), "+f"(d[1]), "+f"(d[2]), "+f"(d[3])
        : "r"(a[0]), "r"(a[1]), "r"(a[2]), "r"(a[3]), "r"(b[0]), "r"(b[1]));
}

// ---------------------------------------------------------------------------
// Kernel: W1, W2 -> fp16
// ---------------------------------------------------------------------------
__global__ void wconv_kernel(const float* __restrict__ W1,
                             const float* __restrict__ W2)
{
    int i = blockIdx.x * 256 + threadIdx.x;
    g_w1[i] = __float2half(W1[i]);
    g_w2[i] = __float2half(W2[i]);
}

// ---------------------------------------------------------------------------
// Kernel: b12 = W2 @ b1 + b2   (fp32, one warp per output row)
// ---------------------------------------------------------------------------
__global__ void bias12_kernel(const float* __restrict__ W2,
                              const float* __restrict__ b1,
                              const float* __restrict__ b2)
{
    int row = blockIdx.x * 8 + (threadIdx.x >> 5);
    int lane = threadIdx.x & 31;
    const float* wr = W2 + (size_t)row * C_;
    float s = 0.0f;
    #pragma unroll 8
    for (int j = lane; j < C_; j += 32) s += wr[j] * b1[j];
    #pragma unroll
    for (int o = 16; o; o >>= 1) s += __shfl_xor_sync(0xFFFFFFFFu, s, o);
    if (lane == 0) g_b12[row] = s + b2[row];
}

// ---------------------------------------------------------------------------
// Kernel: 4:1 mean pool -> tap (fp32) + fp16 copy into g_xa
// ---------------------------------------------------------------------------
__global__ void pool_kernel(const float* __restrict__ x, float* __restrict__ tap)
{
    long i = (long)blockIdx.x * blockDim.x + threadIdx.x;
    if (i >= NELEM) return;
    float4 v = reinterpret_cast<const float4*>(x)[i];
    float m = 0.25f * (v.x + v.y + v.z + v.w);
    tap[i] = m;
    g_xa[i] = __float2half(m);
}

// ---------------------------------------------------------------------------
// W12 GEMM: W12[m][n] = fp16( sum_k W2h[m][k] * W1h[k][n] )
// M=N=K=1024; CTA tile 64(M) x 128(N), KC=64, 3-stage, 256 threads,
// 8 warps in 2(M) x 4(N), warp tile 32x32. 128 CTAs (single wave).
// ---------------------------------------------------------------------------
constexpr int W_KC   = 64;
constexpr int W_ASTR = 144;                 // 128B data + 16B pad
constexpr int W_BSTR = 272;                 // 256B data + 16B pad
constexpr int W_OFB  = 64 * W_ASTR;         // 9216
constexpr int W_STAGE = W_OFB + W_KC * W_BSTR;    // 26624
constexpr int W_STAGES = 3;
constexpr int W_SMEM = W_STAGES * W_STAGE;        // 79872

__global__ __launch_bounds__(256, 1)
void w12_kernel()
{
    extern __shared__ __align__(128) char smem[];
    const uint32_t sb = smem_u32(smem);
    const int tid  = threadIdx.x;
    const int wid  = tid >> 5;
    const int lane = tid & 31;
    const int bn = blockIdx.x * 128;
    const int bm = blockIdx.y * 64;

    const int wm = (wid & 1) * 32;
    const int wn = (wid >> 1) * 32;

    auto load_stage = [&](int ch, int stg) {
        const int k0 = ch * W_KC;
        const uint32_t st = sb + stg * W_STAGE;
        #pragma unroll
        for (int i = 0; i < 2; i++) {          // A: 64 rows x 8 chunks
            int idx = tid + i * 256;
            int r = idx >> 3, c = idx & 7;
            cp_async16(st + r * W_ASTR + c * 16,
                       g_w2 + (size_t)(bm + r) * C_ + k0 + c * 8);
        }
        #pragma unroll
        for (int i = 0; i < 4; i++) {          // B: 64 rows x 16 chunks
            int idx = tid + i * 256;
            int r = idx >> 4, c = idx & 15;
            cp_async16(st + W_OFB + r * W_BSTR + c * 16,
                       g_w1 + (size_t)(k0 + r) * C_ + bn + c * 8);
        }
        cp_commit();
    };

    float acc[2][4][4];
    #pragma unroll
    for (int i = 0; i < 2; i++)
        #pragma unroll
        for (int j = 0; j < 4; j++)
            #pragma unroll
            for (int k = 0; k < 4; k++)
                acc[i][j][k] = 0.0f;

    load_stage(0, 0);
    load_stage(1, 1);

    const int lA_row = lane & 15;
    const int lA_kb  = (lane >> 4) * 16;
    const int lB_row = lane & 15;
    const int lB_nc  = (lane >> 4) * 8;

    for (int ch = 0; ch < C_ / W_KC; ch++) {
        cp_wait<W_STAGES - 2>();
        __syncthreads();
        if (ch + W_STAGES - 1 < C_ / W_KC)
            load_stage(ch + W_STAGES - 1, (ch + W_STAGES - 1) % W_STAGES);
        else
            cp_commit();
        const uint32_t st = sb + (ch % W_STAGES) * W_STAGE;

        #pragma unroll
        for (int ks = 0; ks < 4; ks++) {
            uint32_t b[4][2];
            #pragma unroll
            for (int nq = 0; nq < 2; nq++) {
                uint32_t r[4];
                uint32_t off = (uint32_t)((ks * 16 + lB_row) * W_BSTR
                                          + (wn + nq * 16 + lB_nc) * 2);
                ldsm_x4t(r, st + W_OFB + off);
                b[nq * 2 + 0][0] = r[0]; b[nq * 2 + 0][1] = r[1];
                b[nq * 2 + 1][0] = r[2]; b[nq * 2 + 1][1] = r[3];
            }
            #pragma unroll
            for (int mb = 0; mb < 2; mb++) {
                uint32_t a4[4];
                uint32_t off = (uint32_t)((wm + mb * 16 + lA_row) * W_ASTR
                                          + ks * 32 + lA_kb);
                ldsm_x4(a4, st + off);
                #pragma unroll
                for (int nb = 0; nb < 4; nb++)
                    mma_f16(acc[mb][nb], a4, b[nb]);
            }
        }
    }

    const int r_lo = lane >> 2;
    const int c_lo = (lane & 3) * 2;
    #pragma unroll
    for (int mb = 0; mb < 2; mb++) {
        int gr0 = bm + wm + mb * 16 + r_lo;
        int gr1 = gr0 + 8;
        #pragma unroll
        for (int nb = 0; nb < 4; nb++) {
            int col = bn + wn + nb * 8 + c_lo;
            __half2 h0; h0.x = __float2half(acc[mb][nb][0]);
                        h0.y = __float2half(acc[mb][nb][1]);
            __half2 h1; h1.x = __float2half(acc[mb][nb][2]);
                        h1.y = __float2half(acc[mb][nb][3]);
            *reinterpret_cast<__half2*>(g_w12 + (size_t)gr0 * C_ + col) = h0;
            *reinterpret_cast<__half2*>(g_w12 + (size_t)gr1 * C_ + col) = h1;
        }
    }
}

// ---------------------------------------------------------------------------
// Merged GEMM: grid z in [0,16): z<8 -> ff1 = W1 @ xa + b1 (batch z)
//                                z>=8 -> ff2 = W12 @ xa + b12 (batch z-8)
// CTA tile 128(M) x 256(N), KC=32, 4-stage, 512 threads, warp tile 32x64.
// ---------------------------------------------------------------------------
constexpr int KC = 32;
constexpr int A_STR = 80;
constexpr int B_STR = 528;
constexpr int OF_A = 0;
constexpr int OF_B = 128 * A_STR;
constexpr int STAGE_BYTES = OF_B + KC * B_STR;    // 27136
constexpr int STAGES = 4;
constexpr int GEMM_SMEM = STAGES * STAGE_BYTES;   // 108544
constexpr int NCHUNK = C_ / KC;                   // 32

__global__ __launch_bounds__(512, 1)
void gemm_kernel(const float* __restrict__ b1,
                 float* __restrict__ ff1,
                 float* __restrict__ ff2)
{
    extern __shared__ __align__(128) char smem[];
    const uint32_t sb = smem_u32(smem);

    const int tid  = threadIdx.x;
    const int wid  = tid >> 5;
    const int lane = tid & 31;
    const int bn = blockIdx.x * 256;
    const int bm = blockIdx.y * 128;
    const int bz = blockIdx.z;
    const int batch = bz & 7;
    const bool second = bz >= 8;

    const __half* W    = second ? g_w12 : g_w1;
    const float*  bias = second ? g_b12 : b1;
    float* out = (second ? ff2 : ff1) + (size_t)batch * C_ * T_;
    const __half* Xb = g_xa + (size_t)batch * C_ * T_;

    const int wm = (wid & 3) * 32;
    const int wn = (wid >> 2) * 64;

    const int a_r = tid >> 2;
    const int a_c = tid & 3;
    const int b_k = tid >> 5;
    const int b_c = tid & 31;

    auto load_stage = [&](int ch, int stg) {
        const int k0 = ch * KC;
        const uint32_t st = sb + stg * STAGE_BYTES;
        cp_async16(st + OF_A + a_r * A_STR + a_c * 16,
                   W + (size_t)(bm + a_r) * C_ + k0 + a_c * 8);
        #pragma unroll
        for (int i = 0; i < 2; i++) {
            int kr = b_k + i * 16;
            cp_async16(st + OF_B + kr * B_STR + b_c * 16,
                       Xb + (size_t)(k0 + kr) * T_ + bn + b_c * 8);
        }
        cp_commit();
    };

    float acc[2][8][4];
    #pragma unroll
    for (int i = 0; i < 2; i++)
        #pragma unroll
        for (int j = 0; j < 8; j++)
            #pragma unroll
            for (int k = 0; k < 4; k++)
                acc[i][j][k] = 0.0f;

    load_stage(0, 0);
    load_stage(1, 1);
    load_stage(2, 2);

    const int lA_row = lane & 15;
    const int lA_kb  = (lane >> 4) * 16;
    const int lB_row = lane & 15;
    const int lB_nc  = (lane >> 4) * 8;

    for (int ch = 0; ch < NCHUNK; ch++) {
        cp_wait<STAGES - 2>();
        __syncthreads();

        if (ch + STAGES - 1 < NCHUNK)
            load_stage(ch + STAGES - 1, (ch + STAGES - 1) % STAGES);
        else
            cp_commit();

        const uint32_t st = sb + (ch % STAGES) * STAGE_BYTES;

        #pragma unroll
        for (int ks = 0; ks < 2; ks++) {
            uint32_t b[8][2];
            #pragma unroll
            for (int nq = 0; nq < 4; nq++) {
                uint32_t r[4];
                uint32_t off = (uint32_t)((ks * 16 + lB_row) * B_STR
                                          + (wn + nq * 16 + lB_nc) * 2);
                ldsm_x4t(r, st + OF_B + off);
                b[nq * 2 + 0][0] = r[0]; b[nq * 2 + 0][1] = r[1];
                b[nq * 2 + 1][0] = r[2]; b[nq * 2 + 1][1] = r[3];
            }
            #pragma unroll
            for (int mb = 0; mb < 2; mb++) {
                uint32_t a4[4];
                uint32_t offA = (uint32_t)((wm + mb * 16 + lA_row) * A_STR
                                           + ks * 32 + lA_kb);
                ldsm_x4(a4, st + OF_A + offA);
                #pragma unroll
                for (int nb = 0; nb < 8; nb++)
                    mma_f16(acc[mb][nb], a4, b[nb]);
            }
        }
    }

    const int r_lo = lane >> 2;
    const int c_lo = (lane & 3) * 2;
    #pragma unroll
    for (int mb = 0; mb < 2; mb++) {
        int gr0 = bm + wm + mb * 16 + r_lo;
        int gr1 = gr0 + 8;
        float bv0 = bias[gr0];
        float bv1 = bias[gr1];
        size_t ro0 = (size_t)gr0 * T_ + bn + wn + c_lo;
        size_t ro1 = (size_t)gr1 * T_ + bn + wn + c_lo;
        #pragma unroll
        for (int nb = 0; nb < 8; nb++) {
            *reinterpret_cast<float2*>(out + ro0 + nb * 8) =
                make_float2(acc[mb][nb][0] + bv0, acc[mb][nb][1] + bv0);
            *reinterpret_cast<float2*>(out + ro1 + nb * 8) =
                make_float2(acc[mb][nb][2] + bv1, acc[mb][nb][3] + bv1);
        }
    }
}

// ---------------------------------------------------------------------------
// Kernel: causal windowed mean, via per-group partial sums.
// ---------------------------------------------------------------------------
__global__ void window_kernel(const float* __restrict__ ff2, float* __restrict__ ret)
{
    __shared__ float s[T_];
    __shared__ float pre[T_ / 4];
    const size_t row = blockIdx.x;
    const float4* p4 = reinterpret_cast<const float4*>(ff2 + row * T_);
    float4* s4 = reinterpret_cast<float4*>(s);
    #pragma unroll
    for (int i = 0; i < 2; i++) {
        int idx = threadIdx.x + i * 256;
        float4 v = p4[idx];
        s4[idx] = v;
        pre[idx] = v.x + v.y + v.z + v.w;
    }
    __syncthreads();
    float4* r4 = reinterpret_cast<float4*>(ret + row * T_);
    #pragma unroll
    for (int i = 0; i < 2; i++) {
        int g = threadIdx.x + i * 256;
        float avg;
        if (g >= 4) {
            float sum = s[4 * g] - s[4 * g - 16]
                      + pre[g - 4] + pre[g - 3] + pre[g - 2] + pre[g - 1];
            avg = sum * 0.0625f;
        } else {
            float sum = s[4 * g];
            for (int q = 0; q < g; q++) sum += pre[q];
            avg = sum / (float)(4 * g + 1);
        }
        r4[g] = make_float4(avg, avg, avg, avg);
    }
}

// ---------------------------------------------------------------------------
// Launcher
// ---------------------------------------------------------------------------
extern "C" void kernel_launch(void* const* d_in, const int* in_sizes, int n_in,
                              void* d_out, int out_size)
{
    const float* x  = (const float*)d_in[0];
    const float* W1 = (const float*)d_in[1];
    const float* b1 = (const float*)d_in[2];
    const float* W2 = (const float*)d_in[3];
    const float* b2 = (const float*)d_in[4];

    float* out = (float*)d_out;
    float* ret = out;
    float* tap = out + NELEM;
    float* ff1 = out + 2 * NELEM;
    float* ff2 = out + 3 * NELEM;

    cudaFuncSetAttribute(gemm_kernel,
                         cudaFuncAttributeMaxDynamicSharedMemorySize, GEMM_SMEM);
    cudaFuncSetAttribute(w12_kernel,
                         cudaFuncAttributeMaxDynamicSharedMemorySize, W_SMEM);

    // 1. W -> fp16
    wconv_kernel<<<(C_ * C_) / 256, 256>>>(W1, W2);

    // 2. W12 = fp16(W2 @ W1)  (128 CTAs, single wave)
    {
        dim3 grid(C_ / 128, C_ / 64);
        w12_kernel<<<grid, 256, W_SMEM>>>();
    }

    // 3. b12 = W2 @ b1 + b2
    bias12_kernel<<<C_ / 8, 256>>>(W2, b1, b2);

    // 4. pool -> tap fp32 + g_xa fp16
    pool_kernel<<<(int)(NELEM / 256), 256>>>(x, tap);

    // 5. merged GEMM: ff1 and ff2 in one launch (1024 CTAs)
    {
        dim3 grid(T_ / 256, C_ / 128, 2 * B_);
        gemm_kernel<<<grid, 512, GEMM_SMEM>>>(b1, ff1, ff2);
    }

    // 6. windowed mean + stride-4 broadcast -> ret
    window_kernel<<<B_ * C_, 256>>>(ff2, ret);
}

// round 11
// speedup vs baseline: 4.7035x; 1.0172x over previous
#include <cuda_runtime.h>
#include <cuda_fp16.h>
#include <cstdint>

// ---------------------------------------------------------------------------
// Problem constants
// ---------------------------------------------------------------------------
constexpr int B_ = 8;
constexpr int C_ = 1024;     // M and K of both GEMMs
constexpr int T_ = 2048;     // N of both GEMMs
constexpr long NELEM = (long)B_ * C_ * T_;   // 16,777,216

// d_out layout: [ret | tap | ff1 | ff2], each NELEM floats.

// ---------------------------------------------------------------------------
// Scratch (device globals)
// ---------------------------------------------------------------------------
__device__ __half g_xa[(size_t)B_ * C_ * T_];   // fp16(tap) : shared B operand
__device__ __half g_w1[(size_t)C_ * C_];
__device__ __half g_w2[(size_t)C_ * C_];
__device__ __half g_w12[(size_t)C_ * C_];       // fp16(W2 @ W1)
__device__ float  g_b12[C_];                    // W2 @ b1 + b2

// ---------------------------------------------------------------------------
// helpers
// ---------------------------------------------------------------------------
__device__ __forceinline__ uint32_t smem_u32(const void* p) {
    uint32_t a;
    asm("{ .reg .u64 t; cvta.to.shared.u64 t, %1; cvt.u32.u64 %0, t; }"
        : "=r"(a) : "l"(p));
    return a;
}
__device__ __forceinline__ void cp_async16(uint32_t sdst, const void* gsrc) {
    asm volatile("cp.async.cg.shared.global [%0], [%1], 16;" :: "r"(sdst), "l"(gsrc));
}
__device__ __forceinline__ void cp_commit() {
    asm volatile("cp.async.commit_group;" ::: "memory");
}
template <int N>
__device__ __forceinline__ void cp_wait() {
    asm volatile("cp.async.wait_group %0;" :: "n"(N) : "memory");
}
__device__ __forceinline__ void ldsm_x4(uint32_t (&r)[4], uint32_t addr) {
    asm volatile("ldmatrix.sync.aligned.m8n8.x4.shared.b16 {%0,%1,%2,%3}, [%4];"
        : "=r"(r[0]), "=r"(r[1]), "=r"(r[2]), "=r"(r[3]) : "r"(addr));
}
__device__ __forceinline__ void ldsm_x4t(uint32_t (&r)[4], uint32_t addr) {
    asm volatile("ldmatrix.sync.aligned.m8n8.x4.trans.shared.b16 {%0,%1,%2,%3}, [%4];"
        : "=r"(r[0]), "=r"(r[1]), "=r"(r[2]), "=r"(r[3]) : "r"(addr));
}
__device__ __forceinline__ void mma_f16(float (&d)[4],
                                        const uint32_t (&a)[4],
                                        const uint32_t* b) {
    asm volatile(
        "mma.sync.aligned.m16n8k16.row.col.f32.f16.f16.f32 "
        "{%0,%1,%2,%3}, {%4,%5,%6,%7}, {%8,%9}, {%0,%1,%2,%3};"
        : "+f"(d[0]), "+f"(d[1]), "+f"(d[2]), "+f"(d[3])
        : "r"(a[0]), "r"(a[1]), "r"(a[2]), "r"(a[3]), "r"(b[0]), "r"(b[1]));
}

// ---------------------------------------------------------------------------
// Kernel: W1, W2 -> fp16 (vectorized: 4 elems each per thread)
// ---------------------------------------------------------------------------
__global__ void wconv_kernel(const float* __restrict__ W1,
                             const float* __restrict__ W2)
{
    int i = blockIdx.x * 256 + threadIdx.x;     // float4 index
    float4 v1 = reinterpret_cast<const float4*>(W1)[i];
    float4 v2 = reinterpret_cast<const float4*>(W2)[i];
    __half2 a, b;
    a.x = __float2half(v1.x); a.y = __float2half(v1.y);
    b.x = __float2half(v1.z); b.y = __float2half(v1.w);
    reinterpret_cast<__half2*>(g_w1)[i * 2]     = a;
    reinterpret_cast<__half2*>(g_w1)[i * 2 + 1] = b;
    a.x = __float2half(v2.x); a.y = __float2half(v2.y);
    b.x = __float2half(v2.z); b.y = __float2half(v2.w);
    reinterpret_cast<__half2*>(g_w2)[i * 2]     = a;
    reinterpret_cast<__half2*>(g_w2)[i * 2 + 1] = b;
}

// ---------------------------------------------------------------------------
// Kernel: b12 = W2 @ b1 + b2   (fp32, one warp per output row)
// ---------------------------------------------------------------------------
__global__ void bias12_kernel(const float* __restrict__ W2,
                              const float* __restrict__ b1,
                              const float* __restrict__ b2)
{
    int row = blockIdx.x * 8 + (threadIdx.x >> 5);
    int lane = threadIdx.x & 31;
    const float* wr = W2 + (size_t)row * C_;
    float s = 0.0f;
    #pragma unroll 8
    for (int j = lane; j < C_; j += 32) s += wr[j] * b1[j];
    #pragma unroll
    for (int o = 16; o; o >>= 1) s += __shfl_xor_sync(0xFFFFFFFFu, s, o);
    if (lane == 0) g_b12[row] = s + b2[row];
}

// ---------------------------------------------------------------------------
// Kernel: 4:1 mean pool -> tap (fp32) + fp16 copy into g_xa
// 2 float4 loads per thread, front-batched for MLP.
// ---------------------------------------------------------------------------
__global__ void pool_kernel(const float* __restrict__ x, float* __restrict__ tap)
{
    long i0 = ((long)blockIdx.x * 256 + threadIdx.x) * 2;
    float4 v0 = reinterpret_cast<const float4*>(x)[i0];
    float4 v1 = reinterpret_cast<const float4*>(x)[i0 + 1];
    float m0 = 0.25f * (v0.x + v0.y + v0.z + v0.w);
    float m1 = 0.25f * (v1.x + v1.y + v1.z + v1.w);
    *reinterpret_cast<float2*>(tap + i0) = make_float2(m0, m1);
    __half2 h; h.x = __float2half(m0); h.y = __float2half(m1);
    *reinterpret_cast<__half2*>(g_xa + i0) = h;
}

// ---------------------------------------------------------------------------
// W12 GEMM: W12[m][n] = fp16( sum_k W2h[m][k] * W1h[k][n] )
// M=N=K=1024; CTA tile 64(M) x 128(N), KC=64, 3-stage, 256 threads.
// ---------------------------------------------------------------------------
constexpr int W_KC   = 64;
constexpr int W_ASTR = 144;
constexpr int W_BSTR = 272;
constexpr int W_OFB  = 64 * W_ASTR;               // 9216
constexpr int W_STAGE = W_OFB + W_KC * W_BSTR;    // 26624
constexpr int W_STAGES = 3;
constexpr int W_SMEM = W_STAGES * W_STAGE;        // 79872

__global__ __launch_bounds__(256, 1)
void w12_kernel()
{
    extern __shared__ __align__(128) char smem[];
    const uint32_t sb = smem_u32(smem);
    const int tid  = threadIdx.x;
    const int wid  = tid >> 5;
    const int lane = tid & 31;
    const int bn = blockIdx.x * 128;
    const int bm = blockIdx.y * 64;

    const int wm = (wid & 1) * 32;
    const int wn = (wid >> 1) * 32;

    auto load_stage = [&](int ch, int stg) {
        const int k0 = ch * W_KC;
        const uint32_t st = sb + stg * W_STAGE;
        #pragma unroll
        for (int i = 0; i < 2; i++) {
            int idx = tid + i * 256;
            int r = idx >> 3, c = idx & 7;
            cp_async16(st + r * W_ASTR + c * 16,
                       g_w2 + (size_t)(bm + r) * C_ + k0 + c * 8);
        }
        #pragma unroll
        for (int i = 0; i < 4; i++) {
            int idx = tid + i * 256;
            int r = idx >> 4, c = idx & 15;
            cp_async16(st + W_OFB + r * W_BSTR + c * 16,
                       g_w1 + (size_t)(k0 + r) * C_ + bn + c * 8);
        }
        cp_commit();
    };

    float acc[2][4][4];
    #pragma unroll
    for (int i = 0; i < 2; i++)
        #pragma unroll
        for (int j = 0; j < 4; j++)
            #pragma unroll
            for (int k = 0; k < 4; k++)
                acc[i][j][k] = 0.0f;

    load_stage(0, 0);
    load_stage(1, 1);

    const int lA_row = lane & 15;
    const int lA_kb  = (lane >> 4) * 16;
    const int lB_row = lane & 15;
    const int lB_nc  = (lane >> 4) * 8;

    for (int ch = 0; ch < C_ / W_KC; ch++) {
        cp_wait<W_STAGES - 2>();
        __syncthreads();
        if (ch + W_STAGES - 1 < C_ / W_KC)
            load_stage(ch + W_STAGES - 1, (ch + W_STAGES - 1) % W_STAGES);
        else
            cp_commit();
        const uint32_t st = sb + (ch % W_STAGES) * W_STAGE;

        #pragma unroll
        for (int ks = 0; ks < 4; ks++) {
            uint32_t b[4][2];
            #pragma unroll
            for (int nq = 0; nq < 2; nq++) {
                uint32_t r[4];
                uint32_t off = (uint32_t)((ks * 16 + lB_row) * W_BSTR
                                          + (wn + nq * 16 + lB_nc) * 2);
                ldsm_x4t(r, st + W_OFB + off);
                b[nq * 2 + 0][0] = r[0]; b[nq * 2 + 0][1] = r[1];
                b[nq * 2 + 1][0] = r[2]; b[nq * 2 + 1][1] = r[3];
            }
            #pragma unroll
            for (int mb = 0; mb < 2; mb++) {
                uint32_t a4[4];
                uint32_t off = (uint32_t)((wm + mb * 16 + lA_row) * W_ASTR
                                          + ks * 32 + lA_kb);
                ldsm_x4(a4, st + off);
                #pragma unroll
                for (int nb = 0; nb < 4; nb++)
                    mma_f16(acc[mb][nb], a4, b[nb]);
            }
        }
    }

    const int r_lo = lane >> 2;
    const int c_lo = (lane & 3) * 2;
    #pragma unroll
    for (int mb = 0; mb < 2; mb++) {
        int gr0 = bm + wm + mb * 16 + r_lo;
        int gr1 = gr0 + 8;
        #pragma unroll
        for (int nb = 0; nb < 4; nb++) {
            int col = bn + wn + nb * 8 + c_lo;
            __half2 h0; h0.x = __float2half(acc[mb][nb][0]);
                        h0.y = __float2half(acc[mb][nb][1]);
            __half2 h1; h1.x = __float2half(acc[mb][nb][2]);
                        h1.y = __float2half(acc[mb][nb][3]);
            *reinterpret_cast<__half2*>(g_w12 + (size_t)gr0 * C_ + col) = h0;
            *reinterpret_cast<__half2*>(g_w12 + (size_t)gr1 * C_ + col) = h1;
        }
    }
}

// ---------------------------------------------------------------------------
// Merged GEMM: grid z in [0,16): z<8 -> ff1 = W1 @ xa + b1 (batch z)
//                                z>=8 -> ff2 = W12 @ xa + b12 (batch z-8)
// ---------------------------------------------------------------------------
constexpr int KC = 32;
constexpr int A_STR = 80;
constexpr int B_STR = 528;
constexpr int OF_A = 0;
constexpr int OF_B = 128 * A_STR;
constexpr int STAGE_BYTES = OF_B + KC * B_STR;    // 27136
constexpr int STAGES = 4;
constexpr int GEMM_SMEM = STAGES * STAGE_BYTES;   // 108544
constexpr int NCHUNK = C_ / KC;                   // 32

__global__ __launch_bounds__(512, 1)
void gemm_kernel(const float* __restrict__ b1,
                 float* __restrict__ ff1,
                 float* __restrict__ ff2)
{
    extern __shared__ __align__(128) char smem[];
    const uint32_t sb = smem_u32(smem);

    const int tid  = threadIdx.x;
    const int wid  = tid >> 5;
    const int lane = tid & 31;
    const int bn = blockIdx.x * 256;
    const int bm = blockIdx.y * 128;
    const int bz = blockIdx.z;
    const int batch = bz & 7;
    const bool second = bz >= 8;

    const __half* W    = second ? g_w12 : g_w1;
    const float*  bias = second ? g_b12 : b1;
    float* out = (second ? ff2 : ff1) + (size_t)batch * C_ * T_;
    const __half* Xb = g_xa + (size_t)batch * C_ * T_;

    const int wm = (wid & 3) * 32;
    const int wn = (wid >> 2) * 64;

    const int a_r = tid >> 2;
    const int a_c = tid & 3;
    const int b_k = tid >> 5;
    const int b_c = tid & 31;

    auto load_stage = [&](int ch, int stg) {
        const int k0 = ch * KC;
        const uint32_t st = sb + stg * STAGE_BYTES;
        cp_async16(st + OF_A + a_r * A_STR + a_c * 16,
                   W + (size_t)(bm + a_r) * C_ + k0 + a_c * 8);
        #pragma unroll
        for (int i = 0; i < 2; i++) {
            int kr = b_k + i * 16;
            cp_async16(st + OF_B + kr * B_STR + b_c * 16,
                       Xb + (size_t)(k0 + kr) * T_ + bn + b_c * 8);
        }
        cp_commit();
    };

    float acc[2][8][4];
    #pragma unroll
    for (int i = 0; i < 2; i++)
        #pragma unroll
        for (int j = 0; j < 8; j++)
            #pragma unroll
            for (int k = 0; k < 4; k++)
                acc[i][j][k] = 0.0f;

    load_stage(0, 0);
    load_stage(1, 1);
    load_stage(2, 2);

    const int lA_row = lane & 15;
    const int lA_kb  = (lane >> 4) * 16;
    const int lB_row = lane & 15;
    const int lB_nc  = (lane >> 4) * 8;

    for (int ch = 0; ch < NCHUNK; ch++) {
        cp_wait<STAGES - 2>();
        __syncthreads();

        if (ch + STAGES - 1 < NCHUNK)
            load_stage(ch + STAGES - 1, (ch + STAGES - 1) % STAGES);
        else
            cp_commit();

        const uint32_t st = sb + (ch % STAGES) * STAGE_BYTES;

        #pragma unroll
        for (int ks = 0; ks < 2; ks++) {
            uint32_t b[8][2];
            #pragma unroll
            for (int nq = 0; nq < 4; nq++) {
                uint32_t r[4];
                uint32_t off = (uint32_t)((ks * 16 + lB_row) * B_STR
                                          + (wn + nq * 16 + lB_nc) * 2);
                ldsm_x4t(r, st + OF_B + off);
                b[nq * 2 + 0][0] = r[0]; b[nq * 2 + 0][1] = r[1];
                b[nq * 2 + 1][0] = r[2]; b[nq * 2 + 1][1] = r[3];
            }
            #pragma unroll
            for (int mb = 0; mb < 2; mb++) {
                uint32_t a4[4];
                uint32_t offA = (uint32_t)((wm + mb * 16 + lA_row) * A_STR
                                           + ks * 32 + lA_kb);
                ldsm_x4(a4, st + OF_A + offA);
                #pragma unroll
                for (int nb = 0; nb < 8; nb++)
                    mma_f16(acc[mb][nb], a4, b[nb]);
            }
        }
    }

    const int r_lo = lane >> 2;
    const int c_lo = (lane & 3) * 2;
    #pragma unroll
    for (int mb = 0; mb < 2; mb++) {
        int gr0 = bm + wm + mb * 16 + r_lo;
        int gr1 = gr0 + 8;
        float bv0 = bias[gr0];
        float bv1 = bias[gr1];
        size_t ro0 = (size_t)gr0 * T_ + bn + wn + c_lo;
        size_t ro1 = (size_t)gr1 * T_ + bn + wn + c_lo;
        #pragma unroll
        for (int nb = 0; nb < 8; nb++) {
            *reinterpret_cast<float2*>(out + ro0 + nb * 8) =
                make_float2(acc[mb][nb][0] + bv0, acc[mb][nb][1] + bv0);
            *reinterpret_cast<float2*>(out + ro1 + nb * 8) =
                make_float2(acc[mb][nb][2] + bv1, acc[mb][nb][3] + bv1);
        }
    }
}

// ---------------------------------------------------------------------------
// Kernel: causal windowed mean, via per-group partial sums.
// ---------------------------------------------------------------------------
__global__ void window_kernel(const float* __restrict__ ff2, float* __restrict__ ret)
{
    __shared__ float s[T_];
    __shared__ float pre[T_ / 4];
    const size_t row = blockIdx.x;
    const float4* p4 = reinterpret_cast<const float4*>(ff2 + row * T_);
    float4* s4 = reinterpret_cast<float4*>(s);
    #pragma unroll
    for (int i = 0; i < 2; i++) {
        int idx = threadIdx.x + i * 256;
        float4 v = p4[idx];
        s4[idx] = v;
        pre[idx] = v.x + v.y + v.z + v.w;
    }
    __syncthreads();
    float4* r4 = reinterpret_cast<float4*>(ret + row * T_);
    #pragma unroll
    for (int i = 0; i < 2; i++) {
        int g = threadIdx.x + i * 256;
        float avg;
        if (g >= 4) {
            float sum = s[4 * g] - s[4 * g - 16]
                      + pre[g - 4] + pre[g - 3] + pre[g - 2] + pre[g - 1];
            avg = sum * 0.0625f;
        } else {
            float sum = s[4 * g];
            for (int q = 0; q < g; q++) sum += pre[q];
            avg = sum / (float)(4 * g + 1);
        }
        r4[g] = make_float4(avg, avg, avg, avg);
    }
}

// ---------------------------------------------------------------------------
// Launcher — weights path forked onto a side stream, overlapping pool.
// ---------------------------------------------------------------------------
extern "C" void kernel_launch(void* const* d_in, const int* in_sizes, int n_in,
                              void* d_out, int out_size)
{
    const float* x  = (const float*)d_in[0];
    const float* W1 = (const float*)d_in[1];
    const float* b1 = (const float*)d_in[2];
    const float* W2 = (const float*)d_in[3];
    const float* b2 = (const float*)d_in[4];

    float* out = (float*)d_out;
    float* ret = out;
    float* tap = out + NELEM;
    float* ff1 = out + 2 * NELEM;
    float* ff2 = out + 3 * NELEM;

    static cudaStream_t s1 = nullptr;
    static cudaEvent_t evFork = nullptr, evJoin = nullptr;
    if (!s1) {
        cudaStreamCreateWithFlags(&s1, cudaStreamNonBlocking);
        cudaEventCreateWithFlags(&evFork, cudaEventDisableTiming);
        cudaEventCreateWithFlags(&evJoin, cudaEventDisableTiming);
        cudaFuncSetAttribute(gemm_kernel,
                             cudaFuncAttributeMaxDynamicSharedMemorySize, GEMM_SMEM);
        cudaFuncSetAttribute(w12_kernel,
                             cudaFuncAttributeMaxDynamicSharedMemorySize, W_SMEM);
    }

    // fork: weights path on s1
    cudaEventRecord(evFork, 0);
    cudaStreamWaitEvent(s1, evFork, 0);

    wconv_kernel<<<(C_ * C_) / 1024, 256, 0, s1>>>(W1, W2);
    {
        dim3 grid(C_ / 128, C_ / 64);
        w12_kernel<<<grid, 256, W_SMEM, s1>>>();
    }
    bias12_kernel<<<C_ / 8, 256, 0, s1>>>(W2, b1, b2);
    cudaEventRecord(evJoin, s1);

    // main stream: pool (overlaps weights path)
    pool_kernel<<<(int)(NELEM / 512), 256>>>(x, tap);

    // join before merged GEMM
    cudaStreamWaitEvent(0, evJoin, 0);

    // merged GEMM: ff1 and ff2 in one launch (1024 CTAs)
    {
        dim3 grid(T_ / 256, C_ / 128, 2 * B_);
        gemm_kernel<<<grid, 512, GEMM_SMEM>>>(b1, ff1, ff2);
    }

    // windowed mean + stride-4 broadcast -> ret
    window_kernel<<<B_ * C_, 256>>>(ff2, ret);
}